// round 6
// baseline (speedup 1.0000x reference)
#include <cuda_runtime.h>
#include <cstdint>

// Problem constants
#define PB  4
#define PS  2048
#define PD  1024
#define PH  16
#define PDH 64
#define MROWS (PB*PS)        // 8192
#define O_ELEMS (MROWS*PD)   // 8388608  (offset of attn in d_out)

// ---------------- device scratch (static: no allocations allowed) -------------
__device__ float g_qh[(size_t)PB*PH*PS*PDH]; // [B,H,S,dh]
__device__ float g_kh[(size_t)PB*PH*PS*PDH]; // [B,H,S,dh]
__device__ float g_vt[(size_t)PB*PH*PDH*PS]; // [B,H,dh,S]  (transposed V)
__device__ float g_os[(size_t)PB*PS*PD];     // merged attention output [B,S,D]

// ---------------- tf32 helpers ------------------------------------------------
__device__ __forceinline__ uint32_t f2tf(float x) {
    uint32_t u; asm("cvt.rna.tf32.f32 %0, %1;" : "=r"(u) : "f"(x)); return u;
}
__device__ __forceinline__ void mma8(float* d, const uint32_t* a, const uint32_t* b) {
    asm volatile(
        "mma.sync.aligned.m16n8k8.row.col.f32.tf32.tf32.f32 "
        "{%0,%1,%2,%3},{%4,%5,%6,%7},{%8,%9},{%0,%1,%2,%3};"
        : "+f"(d[0]), "+f"(d[1]), "+f"(d[2]), "+f"(d[3])
        : "r"(a[0]), "r"(a[1]), "r"(a[2]), "r"(a[3]), "r"(b[0]), "r"(b[1]));
}

// ---------------- projection GEMM: C[M,N] = X[M,K] @ W[N,K]^T ----------------
// BM=128, BN=64, BK=32, 256 threads, warp grid 4x2, warp tile 32x32.
// LAYOUT 0: scatter to [B,H,S,dh]   (q/k heads)
// LAYOUT 1: scatter to [B,H,dh,S]   (v transposed)
// LAYOUT 2: flat [M,D] + residual   (fc)
template<int LAYOUT>
__global__ __launch_bounds__(256, 2)
void proj_kernel(const float* __restrict__ X, const float* __restrict__ W,
                 const float* __restrict__ RES, float* __restrict__ OUT)
{
    __shared__ uint32_t As[128 * 36];
    __shared__ uint32_t Bs[64 * 36];
    const int tid = threadIdx.x;
    const int m0 = blockIdx.y * 128;
    const int n0 = blockIdx.x * 64;
    const int warpId = tid >> 5, lane = tid & 31;
    const int g = lane >> 2, t = lane & 3;
    const int wm = warpId >> 1, wn = warpId & 1;
    const int rowBase = wm * 32, colBase = wn * 32;

    float acc[2][4][4];
#pragma unroll
    for (int i = 0; i < 2; i++)
#pragma unroll
        for (int j = 0; j < 4; j++)
#pragma unroll
            for (int r = 0; r < 4; r++) acc[i][j][r] = 0.f;

    for (int kt = 0; kt < PD; kt += 32) {
        // A tile 128x32: 1024 float4, 4 per thread
#pragma unroll
        for (int i = 0; i < 4; i++) {
            int q4 = tid + i * 256;
            int r = q4 >> 3, c4 = q4 & 7;
            float4 v = *(const float4*)(X + (size_t)(m0 + r) * PD + kt + c4 * 4);
            int o = r * 36 + c4 * 4;
            As[o + 0] = f2tf(v.x); As[o + 1] = f2tf(v.y);
            As[o + 2] = f2tf(v.z); As[o + 3] = f2tf(v.w);
        }
        // B tile 64x32: 512 float4, 2 per thread
#pragma unroll
        for (int i = 0; i < 2; i++) {
            int q4 = tid + i * 256;
            int r = q4 >> 3, c4 = q4 & 7;
            float4 v = *(const float4*)(W + (size_t)(n0 + r) * PD + kt + c4 * 4);
            int o = r * 36 + c4 * 4;
            Bs[o + 0] = f2tf(v.x); Bs[o + 1] = f2tf(v.y);
            Bs[o + 2] = f2tf(v.z); Bs[o + 3] = f2tf(v.w);
        }
        __syncthreads();
#pragma unroll
        for (int kk = 0; kk < 32; kk += 8) {
            uint32_t af[2][4], bf[4][2];
#pragma unroll
            for (int mi = 0; mi < 2; mi++) {
                int r = rowBase + mi * 16;
                af[mi][0] = As[(r + g) * 36 + kk + t];
                af[mi][1] = As[(r + g + 8) * 36 + kk + t];
                af[mi][2] = As[(r + g) * 36 + kk + t + 4];
                af[mi][3] = As[(r + g + 8) * 36 + kk + t + 4];
            }
#pragma unroll
            for (int ni = 0; ni < 4; ni++) {
                int c = colBase + ni * 8;
                bf[ni][0] = Bs[(c + g) * 36 + kk + t];
                bf[ni][1] = Bs[(c + g) * 36 + kk + t + 4];
            }
#pragma unroll
            for (int mi = 0; mi < 2; mi++)
#pragma unroll
                for (int ni = 0; ni < 4; ni++)
                    mma8(acc[mi][ni], af[mi], bf[ni]);
        }
        __syncthreads();
    }

    // epilogue
#pragma unroll
    for (int mi = 0; mi < 2; mi++) {
#pragma unroll
        for (int ni = 0; ni < 4; ni++) {
#pragma unroll
            for (int h2 = 0; h2 < 2; h2++) {
                int row = m0 + rowBase + mi * 16 + g + h2 * 8;
                int col = n0 + colBase + ni * 8 + 2 * t;
                float v0 = acc[mi][ni][h2 * 2 + 0];
                float v1 = acc[mi][ni][h2 * 2 + 1];
                if (LAYOUT == 0) {
                    int b = row >> 11, s = row & (PS - 1);
                    int hh = col >> 6, d = col & 63;
                    size_t idx = ((size_t)(b * PH + hh) * PS + s) * PDH + d;
                    OUT[idx] = v0; OUT[idx + 1] = v1;
                } else if (LAYOUT == 1) {
                    int b = row >> 11, s = row & (PS - 1);
                    int hh = col >> 6, d = col & 63;
                    size_t idx = ((size_t)(b * PH + hh) * PDH + d) * PS + s;
                    OUT[idx] = v0; OUT[idx + PS] = v1;
                } else {
                    size_t idx = (size_t)row * PD + col;
                    OUT[idx]     = v0 + RES[idx];
                    OUT[idx + 1] = v1 + RES[idx + 1];
                }
            }
        }
    }
}

// ---------------- scores: S_tile[128x128] = qh @ kh^T * (1/8) ----------------
// grid (kt=16, qt=16, bh=64); warp tile 32x64 (warps 4x2)
__global__ __launch_bounds__(256)
void scores_kernel(const float* __restrict__ QH, const float* __restrict__ KH,
                   float* __restrict__ ATTN)
{
    extern __shared__ float dynsm[];
    uint32_t* As = (uint32_t*)dynsm;             // 128*68
    uint32_t* Bs = (uint32_t*)dynsm + 128 * 68;  // 128*68
    const int tid = threadIdx.x;
    const int kt = blockIdx.x, qt = blockIdx.y, bh = blockIdx.z;
    const int warpId = tid >> 5, lane = tid & 31;
    const int g = lane >> 2, t = lane & 3;
    const int wm = warpId >> 1, wn = warpId & 1;
    const int rowBase = wm * 32, colBase = wn * 64;

    const float* qbase = QH + ((size_t)bh * PS + qt * 128) * PDH;
    const float* kbase = KH + ((size_t)bh * PS + kt * 128) * PDH;

#pragma unroll
    for (int i = 0; i < 8; i++) {
        int q4 = tid + i * 256;
        int r = q4 >> 4, c4 = q4 & 15;
        int o = r * 68 + c4 * 4;
        float4 va = *(const float4*)(qbase + (size_t)r * PDH + c4 * 4);
        As[o + 0] = f2tf(va.x); As[o + 1] = f2tf(va.y);
        As[o + 2] = f2tf(va.z); As[o + 3] = f2tf(va.w);
        float4 vb = *(const float4*)(kbase + (size_t)r * PDH + c4 * 4);
        Bs[o + 0] = f2tf(vb.x); Bs[o + 1] = f2tf(vb.y);
        Bs[o + 2] = f2tf(vb.z); Bs[o + 3] = f2tf(vb.w);
    }
    __syncthreads();

    float acc[2][8][4];
#pragma unroll
    for (int i = 0; i < 2; i++)
#pragma unroll
        for (int j = 0; j < 8; j++)
#pragma unroll
            for (int r = 0; r < 4; r++) acc[i][j][r] = 0.f;

#pragma unroll
    for (int kk = 0; kk < 64; kk += 8) {
        uint32_t af[2][4], bf[8][2];
#pragma unroll
        for (int mi = 0; mi < 2; mi++) {
            int r = rowBase + mi * 16;
            af[mi][0] = As[(r + g) * 68 + kk + t];
            af[mi][1] = As[(r + g + 8) * 68 + kk + t];
            af[mi][2] = As[(r + g) * 68 + kk + t + 4];
            af[mi][3] = As[(r + g + 8) * 68 + kk + t + 4];
        }
#pragma unroll
        for (int ni = 0; ni < 8; ni++) {
            int c = colBase + ni * 8;
            bf[ni][0] = Bs[(c + g) * 68 + kk + t];
            bf[ni][1] = Bs[(c + g) * 68 + kk + t + 4];
        }
#pragma unroll
        for (int mi = 0; mi < 2; mi++)
#pragma unroll
            for (int ni = 0; ni < 8; ni++)
                mma8(acc[mi][ni], af[mi], bf[ni]);
    }

    float* outbase = ATTN + ((size_t)bh * PS + qt * 128) * PS + kt * 128;
#pragma unroll
    for (int mi = 0; mi < 2; mi++)
#pragma unroll
        for (int ni = 0; ni < 8; ni++)
#pragma unroll
            for (int h2 = 0; h2 < 2; h2++) {
                int row = rowBase + mi * 16 + g + h2 * 8;
                int col = colBase + ni * 8 + 2 * t;
                float2 st;
                st.x = acc[mi][ni][h2 * 2 + 0] * 0.125f;
                st.y = acc[mi][ni][h2 * 2 + 1] * 0.125f;
                *(float2*)(outbase + (size_t)row * PS + col) = st;
            }
}

// ------------- softmax (in-place on attn) + AV via tf32 MMA ------------------
// grid (qt=16, bh=64). Block owns 128 query rows.
__global__ __launch_bounds__(256)
void attn_av_kernel(float* __restrict__ ATTN, const float* __restrict__ VT,
                    float* __restrict__ OS)
{
    extern __shared__ float dynsm[];
    uint32_t* Ps  = (uint32_t*)dynsm;                 // 128*132
    uint32_t* Vs  = (uint32_t*)dynsm + 128 * 132;     // 64*132
    float* rowM = dynsm + 128 * 132 + 64 * 132;       // 128
    float* rowI = rowM + 128;                         // 128

    const int tid = threadIdx.x, warpId = tid >> 5, lane = tid & 31;
    const int qt = blockIdx.x, bh = blockIdx.y;
    float* sbase = ATTN + ((size_t)bh * PS + qt * 128) * PS;

    // ---- pass A: per-row max & sum of exp ----
    {
#pragma unroll 1
        for (int i = 0; i < 16; i++) {
            int r = warpId * 16 + i;
            const float4* rp = (const float4*)(sbase + (size_t)r * PS);
            float4 v[16];
#pragma unroll
            for (int j = 0; j < 16; j++) v[j] = rp[lane + j * 32];
            float m = -1e30f;
#pragma unroll
            for (int j = 0; j < 16; j++)
                m = fmaxf(m, fmaxf(fmaxf(v[j].x, v[j].y), fmaxf(v[j].z, v[j].w)));
#pragma unroll
            for (int o = 16; o; o >>= 1) m = fmaxf(m, __shfl_xor_sync(0xffffffffu, m, o));
            float ssum = 0.f;
#pragma unroll
            for (int j = 0; j < 16; j++)
                ssum += __expf(v[j].x - m) + __expf(v[j].y - m) +
                        __expf(v[j].z - m) + __expf(v[j].w - m);
#pragma unroll
            for (int o = 16; o; o >>= 1) ssum += __shfl_xor_sync(0xffffffffu, ssum, o);
            if (lane == 0) { rowM[r] = m; rowI[r] = 1.0f / ssum; }
        }
    }
    __syncthreads();

    const int g = lane >> 2, t = lane & 3;
    const int wm = warpId >> 1, wn = warpId & 1;
    const int rowBase = wm * 32, colBase = wn * 32;
    const float* vbase = VT + (size_t)bh * PDH * PS;

    float acc[2][4][4];
#pragma unroll
    for (int i = 0; i < 2; i++)
#pragma unroll
        for (int j = 0; j < 4; j++)
#pragma unroll
            for (int r = 0; r < 4; r++) acc[i][j][r] = 0.f;

    // ---- pass B: per key-tile, normalize+write attn, accumulate P@V ----
    for (int kt2 = 0; kt2 < 16; kt2++) {
        // P tile 128x128 (read scores, write attn in place, stage tf32)
#pragma unroll
        for (int i = 0; i < 16; i++) {
            int q4 = tid + i * 256;
            int r = q4 >> 5, c4 = q4 & 31;
            float* gp = sbase + (size_t)r * PS + kt2 * 128 + c4 * 4;
            float4 sv = *(const float4*)gp;
            float m = rowM[r], inv = rowI[r];
            float4 p;
            p.x = __expf(sv.x - m) * inv; p.y = __expf(sv.y - m) * inv;
            p.z = __expf(sv.z - m) * inv; p.w = __expf(sv.w - m) * inv;
            *(float4*)gp = p;
            int o = r * 132 + c4 * 4;
            Ps[o + 0] = f2tf(p.x); Ps[o + 1] = f2tf(p.y);
            Ps[o + 2] = f2tf(p.z); Ps[o + 3] = f2tf(p.w);
        }
        // V tile 64x128 from transposed V
#pragma unroll
        for (int i = 0; i < 8; i++) {
            int q4 = tid + i * 256;
            int d = q4 >> 5, c4 = q4 & 31;
            float4 vv = *(const float4*)(vbase + (size_t)d * PS + kt2 * 128 + c4 * 4);
            int o = d * 132 + c4 * 4;
            Vs[o + 0] = f2tf(vv.x); Vs[o + 1] = f2tf(vv.y);
            Vs[o + 2] = f2tf(vv.z); Vs[o + 3] = f2tf(vv.w);
        }
        __syncthreads();
#pragma unroll
        for (int kk = 0; kk < 128; kk += 8) {
            uint32_t af[2][4], bf[4][2];
#pragma unroll
            for (int mi = 0; mi < 2; mi++) {
                int r = rowBase + mi * 16;
                af[mi][0] = Ps[(r + g) * 132 + kk + t];
                af[mi][1] = Ps[(r + g + 8) * 132 + kk + t];
                af[mi][2] = Ps[(r + g) * 132 + kk + t + 4];
                af[mi][3] = Ps[(r + g + 8) * 132 + kk + t + 4];
            }
#pragma unroll
            for (int ni = 0; ni < 4; ni++) {
                int c = colBase + ni * 8;
                bf[ni][0] = Vs[(c + g) * 132 + kk + t];
                bf[ni][1] = Vs[(c + g) * 132 + kk + t + 4];
            }
#pragma unroll
            for (int mi = 0; mi < 2; mi++)
#pragma unroll
                for (int ni = 0; ni < 4; ni++)
                    mma8(acc[mi][ni], af[mi], bf[ni]);
        }
        __syncthreads();
    }

    // epilogue: write merged-head output [B,S,D]
    int b = bh >> 4, hh = bh & 15;
#pragma unroll
    for (int mi = 0; mi < 2; mi++)
#pragma unroll
        for (int ni = 0; ni < 4; ni++)
#pragma unroll
            for (int h2 = 0; h2 < 2; h2++) {
                int row = rowBase + mi * 16 + g + h2 * 8;
                int col = colBase + ni * 8 + 2 * t;
                size_t idx = (size_t)(b * PS + qt * 128 + row) * PD + hh * 64 + col;
                float2 st;
                st.x = acc[mi][ni][h2 * 2 + 0];
                st.y = acc[mi][ni][h2 * 2 + 1];
                *(float2*)(OS + idx) = st;
            }
}

// ---------------- in-place LayerNorm over rows of d_out ----------------------
__global__ __launch_bounds__(256)
void ln_kernel(float* __restrict__ OUT, const float* __restrict__ LW,
               const float* __restrict__ LB)
{
    __shared__ float red[16];
    const int row = blockIdx.x, tid = threadIdx.x;
    float* rp = OUT + (size_t)row * PD;
    float4 v = *(const float4*)(rp + tid * 4);
    float s1 = v.x + v.y + v.z + v.w;
    float s2 = v.x * v.x + v.y * v.y + v.z * v.z + v.w * v.w;
#pragma unroll
    for (int o = 16; o; o >>= 1) {
        s1 += __shfl_xor_sync(0xffffffffu, s1, o);
        s2 += __shfl_xor_sync(0xffffffffu, s2, o);
    }
    int w = tid >> 5, l = tid & 31;
    if (l == 0) { red[w] = s1; red[w + 8] = s2; }
    __syncthreads();
    if (w == 0) {
        float a  = (l < 8) ? red[l] : 0.f;
        float b2 = (l < 8) ? red[l + 8] : 0.f;
#pragma unroll
        for (int o = 4; o; o >>= 1) {
            a  += __shfl_xor_sync(0xffffffffu, a, o);
            b2 += __shfl_xor_sync(0xffffffffu, b2, o);
        }
        if (l == 0) { red[0] = a; red[1] = b2; }
    }
    __syncthreads();
    float mean = red[0] * (1.0f / PD);
    float var  = red[1] * (1.0f / PD) - mean * mean;
    float inv  = rsqrtf(var + 1e-6f);
    float4 w4 = *(const float4*)(LW + tid * 4);
    float4 b4 = *(const float4*)(LB + tid * 4);
    float4 o4;
    o4.x = (v.x - mean) * inv * w4.x + b4.x;
    o4.y = (v.y - mean) * inv * w4.y + b4.y;
    o4.z = (v.z - mean) * inv * w4.z + b4.z;
    o4.w = (v.w - mean) * inv * w4.w + b4.w;
    *(float4*)(rp + tid * 4) = o4;
}

// ---------------- launcher ---------------------------------------------------
extern "C" void kernel_launch(void* const* d_in, const int* in_sizes, int n_in,
                              void* d_out, int out_size)
{
    const float* q   = (const float*)d_in[0];
    const float* k   = (const float*)d_in[1];
    const float* v   = (const float*)d_in[2];
    const float* wq  = (const float*)d_in[3];
    const float* wk  = (const float*)d_in[4];
    const float* wv  = (const float*)d_in[5];
    const float* wfc = (const float*)d_in[6];
    const float* lnw = (const float*)d_in[7];
    const float* lnb = (const float*)d_in[8];
    float* out  = (float*)d_out;
    float* attn = out + (size_t)O_ELEMS;   // outputs concatenated: o then attn

    float *qh, *kh, *vt, *os;
    cudaGetSymbolAddress((void**)&qh, g_qh);
    cudaGetSymbolAddress((void**)&kh, g_kh);
    cudaGetSymbolAddress((void**)&vt, g_vt);
    cudaGetSymbolAddress((void**)&os, g_os);

    const int scores_smem = 2 * 128 * 68 * 4;                    // 69632 B
    const int av_smem     = (128 * 132 + 64 * 132 + 256) * 4;    // 102400 B
    cudaFuncSetAttribute(scores_kernel,
                         cudaFuncAttributeMaxDynamicSharedMemorySize, scores_smem);
    cudaFuncSetAttribute(attn_av_kernel,
                         cudaFuncAttributeMaxDynamicSharedMemorySize, av_smem);

    dim3 blk(256);
    proj_kernel<0><<<dim3(16, 64), blk>>>(q, wq, nullptr, qh);
    proj_kernel<0><<<dim3(16, 64), blk>>>(k, wk, nullptr, kh);
    proj_kernel<1><<<dim3(16, 64), blk>>>(v, wv, nullptr, vt);
    scores_kernel<<<dim3(16, 16, 64), blk, scores_smem>>>(qh, kh, attn);
    attn_av_kernel<<<dim3(16, 64), blk, av_smem>>>(attn, vt, os);
    proj_kernel<2><<<dim3(16, 64), blk>>>(os, wfc, q, out);
    ln_kernel<<<MROWS, 256>>>(out, lnw, lnb);
}

// round 8
// speedup vs baseline: 1.2900x; 1.2900x over previous
#include <cuda_runtime.h>
#include <cstdint>

// Problem constants
#define PB  4
#define PS  2048
#define PD  1024
#define PH  16
#define PDH 64
#define MROWS (PB*PS)        // 8192
#define O_ELEMS (MROWS*PD)   // 8388608  (offset of attn in d_out)

// ---------------- device scratch (static: no allocations allowed) -------------
__device__ float g_qh[(size_t)PB*PH*PS*PDH]; // [B,H,S,dh]
__device__ float g_kh[(size_t)PB*PH*PS*PDH]; // [B,H,S,dh]
__device__ float g_vt[(size_t)PB*PH*PDH*PS]; // [B,H,dh,S]  (transposed V)
__device__ float g_os[(size_t)PB*PS*PD];     // merged attention output [B,S,D]

// ---------------- tf32 helpers ------------------------------------------------
__device__ __forceinline__ uint32_t f2tf(float x) {
    uint32_t u; asm("cvt.rna.tf32.f32 %0, %1;" : "=r"(u) : "f"(x)); return u;
}
__device__ __forceinline__ void mma8(float* d, const uint32_t* a, const uint32_t* b) {
    asm volatile(
        "mma.sync.aligned.m16n8k8.row.col.f32.tf32.tf32.f32 "
        "{%0,%1,%2,%3},{%4,%5,%6,%7},{%8,%9},{%0,%1,%2,%3};"
        : "+f"(d[0]), "+f"(d[1]), "+f"(d[2]), "+f"(d[3])
        : "r"(a[0]), "r"(a[1]), "r"(a[2]), "r"(a[3]), "r"(b[0]), "r"(b[1]));
}

// ---------------- projection GEMM (double-buffered) --------------------------
// C[M,N] = X[M,K] @ W[N,K]^T. BM=128, BN=64, BK=32, 256 thr, warps 4x2 (32x32).
// LAYOUT 0: scatter [B,H,S,dh] | 1: scatter [B,H,dh,S] | 2: flat + residual
template<int LAYOUT>
__global__ __launch_bounds__(256, 2)
void proj_kernel(const float* __restrict__ X, const float* __restrict__ W,
                 const float* __restrict__ RES, float* __restrict__ OUT)
{
    extern __shared__ uint32_t psm[];
    uint32_t* As = psm;                 // 2 buffers of 128*36
    uint32_t* Bs = psm + 2 * 128 * 36;  // 2 buffers of 64*36
    const int tid = threadIdx.x;
    const int m0 = blockIdx.y * 128;
    const int n0 = blockIdx.x * 64;
    const int warpId = tid >> 5, lane = tid & 31;
    const int g = lane >> 2, t = lane & 3;
    const int wm = warpId >> 1, wn = warpId & 1;
    const int rowBase = wm * 32, colBase = wn * 32;

    float4 ra[4], rb[2];
    auto loadRegs = [&](int kt) {
#pragma unroll
        for (int i = 0; i < 4; i++) {
            int q4 = tid + i * 256, r = q4 >> 3, c4 = q4 & 7;
            ra[i] = *(const float4*)(X + (size_t)(m0 + r) * PD + kt + c4 * 4);
        }
#pragma unroll
        for (int i = 0; i < 2; i++) {
            int q4 = tid + i * 256, r = q4 >> 3, c4 = q4 & 7;
            rb[i] = *(const float4*)(W + (size_t)(n0 + r) * PD + kt + c4 * 4);
        }
    };
    auto storeRegs = [&](int buf) {
        uint32_t* Ad = As + buf * (128 * 36);
        uint32_t* Bd = Bs + buf * (64 * 36);
#pragma unroll
        for (int i = 0; i < 4; i++) {
            int q4 = tid + i * 256, r = q4 >> 3, c4 = q4 & 7;
            int o = r * 36 + c4 * 4;
            Ad[o + 0] = f2tf(ra[i].x); Ad[o + 1] = f2tf(ra[i].y);
            Ad[o + 2] = f2tf(ra[i].z); Ad[o + 3] = f2tf(ra[i].w);
        }
#pragma unroll
        for (int i = 0; i < 2; i++) {
            int q4 = tid + i * 256, r = q4 >> 3, c4 = q4 & 7;
            int o = r * 36 + c4 * 4;
            Bd[o + 0] = f2tf(rb[i].x); Bd[o + 1] = f2tf(rb[i].y);
            Bd[o + 2] = f2tf(rb[i].z); Bd[o + 3] = f2tf(rb[i].w);
        }
    };

    float acc[2][4][4];
#pragma unroll
    for (int i = 0; i < 2; i++)
#pragma unroll
        for (int j = 0; j < 4; j++)
#pragma unroll
            for (int r = 0; r < 4; r++) acc[i][j][r] = 0.f;

    loadRegs(0); storeRegs(0); __syncthreads();

    for (int it = 0; it < 32; it++) {
        int cur = it & 1;
        if (it < 31) loadRegs((it + 1) * 32);
        const uint32_t* Ac = As + cur * (128 * 36);
        const uint32_t* Bc = Bs + cur * (64 * 36);
#pragma unroll
        for (int kk = 0; kk < 32; kk += 8) {
            uint32_t af[2][4], bf[4][2];
#pragma unroll
            for (int mi = 0; mi < 2; mi++) {
                int r = rowBase + mi * 16;
                af[mi][0] = Ac[(r + g) * 36 + kk + t];
                af[mi][1] = Ac[(r + g + 8) * 36 + kk + t];
                af[mi][2] = Ac[(r + g) * 36 + kk + t + 4];
                af[mi][3] = Ac[(r + g + 8) * 36 + kk + t + 4];
            }
#pragma unroll
            for (int ni = 0; ni < 4; ni++) {
                int c = colBase + ni * 8;
                bf[ni][0] = Bc[(c + g) * 36 + kk + t];
                bf[ni][1] = Bc[(c + g) * 36 + kk + t + 4];
            }
#pragma unroll
            for (int mi = 0; mi < 2; mi++)
#pragma unroll
                for (int ni = 0; ni < 4; ni++)
                    mma8(acc[mi][ni], af[mi], bf[ni]);
        }
        if (it < 31) storeRegs(cur ^ 1);
        __syncthreads();
    }

    // epilogue
#pragma unroll
    for (int mi = 0; mi < 2; mi++)
#pragma unroll
        for (int ni = 0; ni < 4; ni++)
#pragma unroll
            for (int h2 = 0; h2 < 2; h2++) {
                int row = m0 + rowBase + mi * 16 + g + h2 * 8;
                int col = n0 + colBase + ni * 8 + 2 * t;
                float v0 = acc[mi][ni][h2 * 2 + 0];
                float v1 = acc[mi][ni][h2 * 2 + 1];
                if (LAYOUT == 0) {
                    int b = row >> 11, s = row & (PS - 1);
                    int hh = col >> 6, d = col & 63;
                    size_t idx = ((size_t)(b * PH + hh) * PS + s) * PDH + d;
                    OUT[idx] = v0; OUT[idx + 1] = v1;
                } else if (LAYOUT == 1) {
                    int b = row >> 11, s = row & (PS - 1);
                    int hh = col >> 6, d = col & 63;
                    size_t idx = ((size_t)(b * PH + hh) * PDH + d) * PS + s;
                    OUT[idx] = v0; OUT[idx + PS] = v1;
                } else {
                    size_t idx = (size_t)row * PD + col;
                    OUT[idx]     = v0 + RES[idx];
                    OUT[idx + 1] = v1 + RES[idx + 1];
                }
            }
}

// ---------------- fused attention: scores + softmax + attn-write + P@V -------
// Block = (bh, qt): 128 query rows of one head. 256 threads, 8 warps (4x2).
// Pass 1: stream K (double-buffered), S on tensor cores, online row stats only.
// Pass 2: re-stream K (L2-hot), recompute S (bitwise identical), p=exp(v-m)*inv,
//         write attn (only big DRAM write), stage tf32 P, accumulate P@V.
__global__ __launch_bounds__(256)
void fused_attn_kernel(const float* __restrict__ QH, const float* __restrict__ KH,
                       const float* __restrict__ VT,
                       float* __restrict__ ATTN, float* __restrict__ OS)
{
    extern __shared__ uint32_t sm[];
    uint32_t* Qs = sm;                      // 128*68
    uint32_t* Kb = sm + 8704;               // 2 * 128*68
    uint32_t* Vb = sm + 8704 + 17408;       // 64*132
    uint32_t* Ps = sm + 8704 + 17408 + 8448;// 128*132
    float* sM   = (float*)(sm + 51456);     // 2*128
    float* sS   = sM + 256;                 // 2*128
    float* rowM = sS + 256;                 // 128
    float* rowI = rowM + 128;               // 128

    const int tid = threadIdx.x;
    const int qt = blockIdx.x, bh = blockIdx.y;
    const int warpId = tid >> 5, lane = tid & 31;
    const int g = lane >> 2, t = lane & 3;
    const int wm = warpId >> 1, wn = warpId & 1;
    const int rowBase = wm * 32;

    const float* qbase = QH + ((size_t)bh * PS + qt * 128) * PDH;
    const float* kbase = KH + (size_t)bh * PS * PDH;
    const float* vbase = VT + (size_t)bh * PDH * PS;
    float* outbase = ATTN + ((size_t)bh * PS + qt * 128) * PS;

    // load Q tile once (tf32)
#pragma unroll
    for (int i = 0; i < 8; i++) {
        int q4 = tid + i * 256, r = q4 >> 4, c4 = q4 & 15;
        float4 v = *(const float4*)(qbase + (size_t)r * PDH + c4 * 4);
        int o = r * 68 + c4 * 4;
        Qs[o + 0] = f2tf(v.x); Qs[o + 1] = f2tf(v.y);
        Qs[o + 2] = f2tf(v.z); Qs[o + 3] = f2tf(v.w);
    }

    float mrun[4], srun[4];
#pragma unroll
    for (int i = 0; i < 4; i++) { mrun[i] = -1e30f; srun[i] = 0.f; }

    float acc[2][8][4];

    // ---------------- pass 1: stats only ----------------
    {
        float4 kr[8];
        auto loadK = [&](int kt) {
            const float* kb = kbase + (size_t)kt * 128 * PDH;
#pragma unroll
            for (int i = 0; i < 8; i++) {
                int q4 = tid + i * 256, r = q4 >> 4, c4 = q4 & 15;
                kr[i] = *(const float4*)(kb + (size_t)r * PDH + c4 * 4);
            }
        };
        auto storeK = [&](int buf) {
            uint32_t* kd = Kb + buf * 8704;
#pragma unroll
            for (int i = 0; i < 8; i++) {
                int q4 = tid + i * 256, r = q4 >> 4, c4 = q4 & 15;
                int o = r * 68 + c4 * 4;
                kd[o + 0] = f2tf(kr[i].x); kd[o + 1] = f2tf(kr[i].y);
                kd[o + 2] = f2tf(kr[i].z); kd[o + 3] = f2tf(kr[i].w);
            }
        };

        loadK(0); storeK(0);
        __syncthreads();

        for (int kt = 0; kt < 16; kt++) {
            int cur = kt & 1;
            if (kt < 15) loadK(kt + 1);
            const uint32_t* kd = Kb + cur * 8704;
#pragma unroll
            for (int i = 0; i < 2; i++)
#pragma unroll
                for (int j = 0; j < 8; j++)
#pragma unroll
                    for (int r = 0; r < 4; r++) acc[i][j][r] = 0.f;
#pragma unroll
            for (int kk = 0; kk < 64; kk += 8) {
                uint32_t af[2][4], bf[8][2];
#pragma unroll
                for (int mi = 0; mi < 2; mi++) {
                    int r = rowBase + mi * 16;
                    af[mi][0] = Qs[(r + g) * 68 + kk + t];
                    af[mi][1] = Qs[(r + g + 8) * 68 + kk + t];
                    af[mi][2] = Qs[(r + g) * 68 + kk + t + 4];
                    af[mi][3] = Qs[(r + g + 8) * 68 + kk + t + 4];
                }
#pragma unroll
                for (int ni = 0; ni < 8; ni++) {
                    int c = wn * 64 + ni * 8;
                    bf[ni][0] = kd[(c + g) * 68 + kk + t];
                    bf[ni][1] = kd[(c + g) * 68 + kk + t + 4];
                }
#pragma unroll
                for (int mi = 0; mi < 2; mi++)
#pragma unroll
                    for (int ni = 0; ni < 8; ni++)
                        mma8(acc[mi][ni], af[mi], bf[ni]);
            }
            // online stats over this 128-col tile (per 64-col warp stripe)
#pragma unroll
            for (int mi = 0; mi < 2; mi++)
#pragma unroll
                for (int h2 = 0; h2 < 2; h2++) {
                    int idx = mi * 2 + h2;
                    float vmax = -1e30f;
#pragma unroll
                    for (int ni = 0; ni < 8; ni++) {
                        vmax = fmaxf(vmax, acc[mi][ni][h2 * 2 + 0]);
                        vmax = fmaxf(vmax, acc[mi][ni][h2 * 2 + 1]);
                    }
                    vmax = fmaxf(vmax, __shfl_xor_sync(0xffffffffu, vmax, 1));
                    vmax = fmaxf(vmax, __shfl_xor_sync(0xffffffffu, vmax, 2));
                    float mn = fmaxf(mrun[idx], vmax * 0.125f);
                    float ps = 0.f;
#pragma unroll
                    for (int ni = 0; ni < 8; ni++) {
                        ps += __expf(acc[mi][ni][h2 * 2 + 0] * 0.125f - mn);
                        ps += __expf(acc[mi][ni][h2 * 2 + 1] * 0.125f - mn);
                    }
                    ps += __shfl_xor_sync(0xffffffffu, ps, 1);
                    ps += __shfl_xor_sync(0xffffffffu, ps, 2);
                    srun[idx] = srun[idx] * __expf(mrun[idx] - mn) + ps;
                    mrun[idx] = mn;
                }
            if (kt < 15) storeK(cur ^ 1);
            __syncthreads();
        }
    }

    // merge the two 1024-col stripes per row
    if ((lane & 3) == 0) {
#pragma unroll
        for (int mi = 0; mi < 2; mi++)
#pragma unroll
            for (int h2 = 0; h2 < 2; h2++) {
                int row = rowBase + mi * 16 + h2 * 8 + g;
                sM[wn * 128 + row] = mrun[mi * 2 + h2];
                sS[wn * 128 + row] = srun[mi * 2 + h2];
            }
    }
    __syncthreads();
    if (tid < 128) {
        float m0 = sM[tid], m1 = sM[128 + tid];
        float m = fmaxf(m0, m1);
        float s = sS[tid] * __expf(m0 - m) + sS[128 + tid] * __expf(m1 - m);
        rowM[tid] = m; rowI[tid] = 1.0f / s;
    }
    __syncthreads();

    float rm[4], ri[4];
#pragma unroll
    for (int mi = 0; mi < 2; mi++)
#pragma unroll
        for (int h2 = 0; h2 < 2; h2++) {
            int row = rowBase + mi * 16 + h2 * 8 + g;
            rm[mi * 2 + h2] = rowM[row];
            ri[mi * 2 + h2] = rowI[row];
        }

    float oacc[2][4][4];
#pragma unroll
    for (int i = 0; i < 2; i++)
#pragma unroll
        for (int j = 0; j < 4; j++)
#pragma unroll
            for (int r = 0; r < 4; r++) oacc[i][j][r] = 0.f;

    const int colB2 = wn * 32;

    // ---------------- pass 2: recompute S -> p -> attn write + P@V ----------
    for (int kt = 0; kt < 16; kt++) {
        // load K tile (buffer 0) + V tile
        {
            const float* kb = kbase + (size_t)kt * 128 * PDH;
#pragma unroll
            for (int i = 0; i < 8; i++) {
                int q4 = tid + i * 256, r = q4 >> 4, c4 = q4 & 15;
                float4 v = *(const float4*)(kb + (size_t)r * PDH + c4 * 4);
                int o = r * 68 + c4 * 4;
                Kb[o + 0] = f2tf(v.x); Kb[o + 1] = f2tf(v.y);
                Kb[o + 2] = f2tf(v.z); Kb[o + 3] = f2tf(v.w);
            }
#pragma unroll
            for (int i = 0; i < 8; i++) {
                int q4 = tid + i * 256, d = q4 >> 5, c4 = q4 & 31;
                float4 v = *(const float4*)(vbase + (size_t)d * PS + kt * 128 + c4 * 4);
                int o = d * 132 + c4 * 4;
                Vb[o + 0] = f2tf(v.x); Vb[o + 1] = f2tf(v.y);
                Vb[o + 2] = f2tf(v.z); Vb[o + 3] = f2tf(v.w);
            }
        }
        __syncthreads();

        // recompute S (identical math to pass 1)
#pragma unroll
        for (int i = 0; i < 2; i++)
#pragma unroll
            for (int j = 0; j < 8; j++)
#pragma unroll
                for (int r = 0; r < 4; r++) acc[i][j][r] = 0.f;
#pragma unroll
        for (int kk = 0; kk < 64; kk += 8) {
            uint32_t af[2][4], bf[8][2];
#pragma unroll
            for (int mi = 0; mi < 2; mi++) {
                int r = rowBase + mi * 16;
                af[mi][0] = Qs[(r + g) * 68 + kk + t];
                af[mi][1] = Qs[(r + g + 8) * 68 + kk + t];
                af[mi][2] = Qs[(r + g) * 68 + kk + t + 4];
                af[mi][3] = Qs[(r + g + 8) * 68 + kk + t + 4];
            }
#pragma unroll
            for (int ni = 0; ni < 8; ni++) {
                int c = wn * 64 + ni * 8;
                bf[ni][0] = Kb[(c + g) * 68 + kk + t];
                bf[ni][1] = Kb[(c + g) * 68 + kk + t + 4];
            }
#pragma unroll
            for (int mi = 0; mi < 2; mi++)
#pragma unroll
                for (int ni = 0; ni < 8; ni++)
                    mma8(acc[mi][ni], af[mi], bf[ni]);
        }

        // p = exp(v - m) * inv ; write attn to gmem; stage tf32 P in smem
#pragma unroll
        for (int mi = 0; mi < 2; mi++)
#pragma unroll
            for (int ni = 0; ni < 8; ni++)
#pragma unroll
                for (int h2 = 0; h2 < 2; h2++) {
                    int idx = mi * 2 + h2;
                    int row = rowBase + mi * 16 + h2 * 8 + g;
                    int cl = wn * 64 + ni * 8 + 2 * t;
                    float p0 = __expf(acc[mi][ni][h2 * 2 + 0] * 0.125f - rm[idx]) * ri[idx];
                    float p1 = __expf(acc[mi][ni][h2 * 2 + 1] * 0.125f - rm[idx]) * ri[idx];
                    float2 st; st.x = p0; st.y = p1;
                    *(float2*)(outbase + (size_t)row * PS + kt * 128 + cl) = st;
                    Ps[row * 132 + cl]     = f2tf(p0);
                    Ps[row * 132 + cl + 1] = f2tf(p1);
                }
        __syncthreads();

        // P @ V  (warp tile 32x32 over O[128x64])
#pragma unroll
        for (int kk = 0; kk < 128; kk += 8) {
            uint32_t afv[2][4], bfv[4][2];
#pragma unroll
            for (int mi = 0; mi < 2; mi++) {
                int r = rowBase + mi * 16;
                afv[mi][0] = Ps[(r + g) * 132 + kk + t];
                afv[mi][1] = Ps[(r + g + 8) * 132 + kk + t];
                afv[mi][2] = Ps[(r + g) * 132 + kk + t + 4];
                afv[mi][3] = Ps[(r + g + 8) * 132 + kk + t + 4];
            }
#pragma unroll
            for (int ni = 0; ni < 4; ni++) {
                int c = colB2 + ni * 8;
                bfv[ni][0] = Vb[(c + g) * 132 + kk + t];
                bfv[ni][1] = Vb[(c + g) * 132 + kk + t + 4];
            }
#pragma unroll
            for (int mi = 0; mi < 2; mi++)
#pragma unroll
                for (int ni = 0; ni < 4; ni++)
                    mma8(oacc[mi][ni], afv[mi], bfv[ni]);
        }
        __syncthreads();
    }

    // O epilogue -> merged [B,S,D]
    int b = bh >> 4, hh = bh & 15;
#pragma unroll
    for (int mi = 0; mi < 2; mi++)
#pragma unroll
        for (int ni = 0; ni < 4; ni++)
#pragma unroll
            for (int h2 = 0; h2 < 2; h2++) {
                int row = rowBase + mi * 16 + h2 * 8 + g;
                int col = colB2 + ni * 8 + 2 * t;
                size_t idx = (size_t)(b * PS + qt * 128 + row) * PD + hh * 64 + col;
                float2 st;
                st.x = oacc[mi][ni][h2 * 2 + 0];
                st.y = oacc[mi][ni][h2 * 2 + 1];
                *(float2*)(OS + idx) = st;
            }
}

// ---------------- in-place LayerNorm over rows of d_out ----------------------
__global__ __launch_bounds__(256)
void ln_kernel(float* __restrict__ OUT, const float* __restrict__ LW,
               const float* __restrict__ LB)
{
    __shared__ float red[16];
    const int row = blockIdx.x, tid = threadIdx.x;
    float* rp = OUT + (size_t)row * PD;
    float4 v = *(const float4*)(rp + tid * 4);
    float s1 = v.x + v.y + v.z + v.w;
    float s2 = v.x * v.x + v.y * v.y + v.z * v.z + v.w * v.w;
#pragma unroll
    for (int o = 16; o; o >>= 1) {
        s1 += __shfl_xor_sync(0xffffffffu, s1, o);
        s2 += __shfl_xor_sync(0xffffffffu, s2, o);
    }
    int w = tid >> 5, l = tid & 31;
    if (l == 0) { red[w] = s1; red[w + 8] = s2; }
    __syncthreads();
    if (w == 0) {
        float a  = (l < 8) ? red[l] : 0.f;
        float b2 = (l < 8) ? red[l + 8] : 0.f;
#pragma unroll
        for (int o = 4; o; o >>= 1) {
            a  += __shfl_xor_sync(0xffffffffu, a, o);
            b2 += __shfl_xor_sync(0xffffffffu, b2, o);
        }
        if (l == 0) { red[0] = a; red[1] = b2; }
    }
    __syncthreads();
    float mean = red[0] * (1.0f / PD);
    float var  = red[1] * (1.0f / PD) - mean * mean;
    float inv  = rsqrtf(var + 1e-6f);
    float4 w4 = *(const float4*)(LW + tid * 4);
    float4 b4 = *(const float4*)(LB + tid * 4);
    float4 o4;
    o4.x = (v.x - mean) * inv * w4.x + b4.x;
    o4.y = (v.y - mean) * inv * w4.y + b4.y;
    o4.z = (v.z - mean) * inv * w4.z + b4.z;
    o4.w = (v.w - mean) * inv * w4.w + b4.w;
    *(float4*)(rp + tid * 4) = o4;
}

// ---------------- launcher ---------------------------------------------------
extern "C" void kernel_launch(void* const* d_in, const int* in_sizes, int n_in,
                              void* d_out, int out_size)
{
    const float* q   = (const float*)d_in[0];
    const float* k   = (const float*)d_in[1];
    const float* v   = (const float*)d_in[2];
    const float* wq  = (const float*)d_in[3];
    const float* wk  = (const float*)d_in[4];
    const float* wv  = (const float*)d_in[5];
    const float* wfc = (const float*)d_in[6];
    const float* lnw = (const float*)d_in[7];
    const float* lnb = (const float*)d_in[8];
    float* out  = (float*)d_out;
    float* attn = out + (size_t)O_ELEMS;   // outputs concatenated: o then attn

    float *qh, *kh, *vt, *os;
    cudaGetSymbolAddress((void**)&qh, g_qh);
    cudaGetSymbolAddress((void**)&kh, g_kh);
    cudaGetSymbolAddress((void**)&vt, g_vt);
    cudaGetSymbolAddress((void**)&os, g_os);

    const int proj_smem  = (2 * 128 * 36 + 2 * 64 * 36) * 4;   // 55296 B
    const int fused_smem = 52224 * 4;                          // 208896 B
    cudaFuncSetAttribute(proj_kernel<0>,
                         cudaFuncAttributeMaxDynamicSharedMemorySize, proj_smem);
    cudaFuncSetAttribute(proj_kernel<1>,
                         cudaFuncAttributeMaxDynamicSharedMemorySize, proj_smem);
    cudaFuncSetAttribute(proj_kernel<2>,
                         cudaFuncAttributeMaxDynamicSharedMemorySize, proj_smem);
    cudaFuncSetAttribute(fused_attn_kernel,
                         cudaFuncAttributeMaxDynamicSharedMemorySize, fused_smem);

    dim3 blk(256);
    proj_kernel<0><<<dim3(16, 64), blk, proj_smem>>>(q, wq, nullptr, qh);
    proj_kernel<0><<<dim3(16, 64), blk, proj_smem>>>(k, wk, nullptr, kh);
    proj_kernel<1><<<dim3(16, 64), blk, proj_smem>>>(v, wv, nullptr, vt);
    fused_attn_kernel<<<dim3(16, 64), blk, fused_smem>>>(qh, kh, vt, attn, os);
    proj_kernel<2><<<dim3(16, 64), blk, proj_smem>>>(os, wfc, q, out);
    ln_kernel<<<MROWS, 256>>>(out, lnw, lnb);
}